// round 5
// baseline (speedup 1.0000x reference)
#include <cuda_runtime.h>
#include <cuda_bf16.h>

#define BATCH 16384
#define CTX 10
#define EMB 256

__global__ void zero_out_kernel(float* out) {
    out[0] = 0.0f;
}

// One warp handles BOTH the positive and negative sample of one batch element:
// two independent gather streams per warp, branchless, half the blocks.
__global__ __launch_bounds__(256, 3) void cbow_loss_kernel(
    const int* __restrict__ pos_u,
    const int* __restrict__ pos_w,
    const int* __restrict__ neg_u,
    const int* __restrict__ neg_w,
    const float* __restrict__ u_weight,
    const float* __restrict__ w_weight,
    float* __restrict__ out)
{
    const int b = blockIdx.x * 8 + (threadIdx.x >> 5);   // batch element
    const int lane = threadIdx.x & 31;

    const float4* __restrict__ u4 = reinterpret_cast<const float4*>(u_weight);
    const float4* __restrict__ w4 = reinterpret_cast<const float4*>(w_weight);

    // ---- w rows for both signs, issued first ----
    const long long wp = (long long)__ldg(&pos_w[b]) * (EMB / 4);
    const long long wn = (long long)__ldg(&neg_w[b]) * (EMB / 4);
    const float4 wp0 = __ldg(&w4[wp + lane]);
    const float4 wp1 = __ldg(&w4[wp + 32 + lane]);
    const float4 wn0 = __ldg(&w4[wn + lane]);
    const float4 wn1 = __ldg(&w4[wn + 32 + lane]);

    const int* __restrict__ ip = pos_u + b * CTX;
    const int* __restrict__ in_ = neg_u + b * CTX;

    // ---- preload rows 0,1 for both streams (4 KB in flight / warp) ----
    long long rp = (long long)__ldg(&ip[0]) * (EMB / 4);
    long long rn = (long long)__ldg(&in_[0]) * (EMB / 4);
    float4 pa0 = __ldg(&u4[rp + lane]);
    float4 pa1 = __ldg(&u4[rp + 32 + lane]);
    float4 na0 = __ldg(&u4[rn + lane]);
    float4 na1 = __ldg(&u4[rn + 32 + lane]);

    rp = (long long)__ldg(&ip[1]) * (EMB / 4);
    rn = (long long)__ldg(&in_[1]) * (EMB / 4);
    float4 pb0 = __ldg(&u4[rp + lane]);
    float4 pb1 = __ldg(&u4[rp + 32 + lane]);
    float4 nb0 = __ldg(&u4[rn + lane]);
    float4 nb1 = __ldg(&u4[rn + 32 + lane]);

    float accp = 0.0f, accn = 0.0f;

    #pragma unroll
    for (int c = 0; c < CTX; c++) {
        float4 pc0, pc1, nc0, nc1;
        if (c + 2 < CTX) {
            // index loads are warp-uniform single-line L1 hits
            const long long r2p = (long long)__ldg(&ip[c + 2]) * (EMB / 4);
            const long long r2n = (long long)__ldg(&in_[c + 2]) * (EMB / 4);
            pc0 = __ldg(&u4[r2p + lane]);
            pc1 = __ldg(&u4[r2p + 32 + lane]);
            nc0 = __ldg(&u4[r2n + lane]);
            nc1 = __ldg(&u4[r2n + 32 + lane]);
        }
        accp = fmaf(pa0.x, wp0.x, accp);
        accp = fmaf(pa0.y, wp0.y, accp);
        accp = fmaf(pa0.z, wp0.z, accp);
        accp = fmaf(pa0.w, wp0.w, accp);
        accp = fmaf(pa1.x, wp1.x, accp);
        accp = fmaf(pa1.y, wp1.y, accp);
        accp = fmaf(pa1.z, wp1.z, accp);
        accp = fmaf(pa1.w, wp1.w, accp);
        accn = fmaf(na0.x, wn0.x, accn);
        accn = fmaf(na0.y, wn0.y, accn);
        accn = fmaf(na0.z, wn0.z, accn);
        accn = fmaf(na0.w, wn0.w, accn);
        accn = fmaf(na1.x, wn1.x, accn);
        accn = fmaf(na1.y, wn1.y, accn);
        accn = fmaf(na1.z, wn1.z, accn);
        accn = fmaf(na1.w, wn1.w, accn);
        pa0 = pb0; pa1 = pb1; na0 = nb0; na1 = nb1;
        pb0 = pc0; pb1 = pc1; nb0 = nc0; nb1 = nc1;
    }

    // ---- warp reduce both dots ----
    #pragma unroll
    for (int off = 16; off > 0; off >>= 1) {
        accp += __shfl_xor_sync(0xFFFFFFFFu, accp, off);
        accn += __shfl_xor_sync(0xFFFFFFFFu, accn, off);
    }

    __shared__ float warp_part[8];
    if (lane == 0) {
        // loss = -logsig(accp) - logsig(-accn)
        const float sp = accp, sn = -accn;
        const float lp = fminf(sp, 0.0f) - log1pf(__expf(-fabsf(sp)));
        const float ln = fminf(sn, 0.0f) - log1pf(__expf(-fabsf(sn)));
        warp_part[threadIdx.x >> 5] = -(lp + ln);
    }
    __syncthreads();

    if (threadIdx.x == 0) {
        float blk = 0.0f;
        #pragma unroll
        for (int w = 0; w < 8; w++) blk += warp_part[w];
        atomicAdd(out, blk);
    }
}

extern "C" void kernel_launch(void* const* d_in, const int* in_sizes, int n_in,
                              void* d_out, int out_size) {
    const int*   pos_u    = (const int*)d_in[0];
    const int*   pos_w    = (const int*)d_in[1];
    const int*   neg_u    = (const int*)d_in[2];
    const int*   neg_w    = (const int*)d_in[3];
    const float* u_weight = (const float*)d_in[4];
    const float* w_weight = (const float*)d_in[5];
    float* out = (float*)d_out;

    zero_out_kernel<<<1, 1>>>(out);

    // one warp per batch element (pos+neg fused), 8 warps/block
    const int blocks = BATCH / 8;  // 2048
    cbow_loss_kernel<<<blocks, 256>>>(pos_u, pos_w, neg_u, neg_w,
                                      u_weight, w_weight, out);
}

// round 6
// speedup vs baseline: 1.0007x; 1.0007x over previous
#include <cuda_runtime.h>
#include <cuda_bf16.h>

#define BATCH 16384
#define CTX 10
#define EMB 256

#define NBLOCKS 444          // 148 SMs x 3 resident blocks = single wave
#define NTHREADS 256
#define NWARPS (NBLOCKS * NTHREADS / 32)

__device__ float    g_scratch = 0.0f;
__device__ unsigned g_count   = 0u;

// Persistent single-wave kernel. Each warp grid-strides over the 32768
// (batch, sign) tasks; per-task body = R2 shape (best measured).
__global__ __launch_bounds__(NTHREADS, 3) void cbow_loss_kernel(
    const int* __restrict__ pos_u,
    const int* __restrict__ pos_w,
    const int* __restrict__ neg_u,
    const int* __restrict__ neg_w,
    const float* __restrict__ u_weight,
    const float* __restrict__ w_weight,
    float* __restrict__ out)
{
    const int lane = threadIdx.x & 31;
    const int warp_global = (blockIdx.x * NTHREADS + threadIdx.x) >> 5;

    float loss = 0.0f;

    for (int task = warp_global; task < 2 * BATCH; task += NWARPS) {
        int b = task;
        const bool is_neg = (b >= BATCH);
        if (is_neg) b -= BATCH;

        const int* __restrict__ uidx = is_neg ? neg_u : pos_u;
        const int* __restrict__ widx = is_neg ? neg_w : pos_w;

        // w row first
        const long long wrow = (long long)__ldg(&widx[b]) * EMB;
        const float4* __restrict__ wr = reinterpret_cast<const float4*>(w_weight + wrow);
        const float4 w0 = __ldg(&wr[lane]);
        const float4 w1 = __ldg(&wr[lane + 32]);

        // all 10 context indices up front
        int ui[CTX];
        #pragma unroll
        for (int c = 0; c < CTX; c++)
            ui[c] = __ldg(&uidx[b * CTX + c]);

        #define UROW(c) (reinterpret_cast<const float4*>(u_weight + (long long)ui[(c)] * EMB))

        // 3-deep pipeline
        float4 a0 = __ldg(&UROW(0)[lane]);
        float4 a1 = __ldg(&UROW(0)[lane + 32]);
        float4 b0 = __ldg(&UROW(1)[lane]);
        float4 b1 = __ldg(&UROW(1)[lane + 32]);

        float acc = 0.0f;

        #pragma unroll
        for (int c = 0; c < CTX; c++) {
            float4 n0, n1;
            if (c + 2 < CTX) {
                n0 = __ldg(&UROW(c + 2)[lane]);
                n1 = __ldg(&UROW(c + 2)[lane + 32]);
            }
            acc = fmaf(a0.x, w0.x, acc);
            acc = fmaf(a0.y, w0.y, acc);
            acc = fmaf(a0.z, w0.z, acc);
            acc = fmaf(a0.w, w0.w, acc);
            acc = fmaf(a1.x, w1.x, acc);
            acc = fmaf(a1.y, w1.y, acc);
            acc = fmaf(a1.z, w1.z, acc);
            acc = fmaf(a1.w, w1.w, acc);
            a0 = b0; a1 = b1;
            b0 = n0; b1 = n1;
        }
        #undef UROW

        // warp reduce this task's dot
        #pragma unroll
        for (int off = 16; off > 0; off >>= 1)
            acc += __shfl_xor_sync(0xFFFFFFFFu, acc, off);

        // every lane computes the same logsigmoid (cheap, avoids divergence)
        const float s  = is_neg ? -acc : acc;
        const float ls = fminf(s, 0.0f) - log1pf(__expf(-fabsf(s)));
        loss -= ls;
    }

    // block reduce: one value per warp (all lanes hold the same loss)
    __shared__ float warp_part[8];
    if (lane == 0)
        warp_part[threadIdx.x >> 5] = loss;
    __syncthreads();

    if (threadIdx.x == 0) {
        float blk = 0.0f;
        #pragma unroll
        for (int w = 0; w < 8; w++) blk += warp_part[w];
        atomicAdd(&g_scratch, blk);
        __threadfence();
        // last block finishing publishes the result and resets state so the
        // launch is deterministic under graph replay
        if (atomicInc(&g_count, NBLOCKS - 1) == NBLOCKS - 1) {
            out[0] = g_scratch;
            g_scratch = 0.0f;
            __threadfence();
        }
    }
}

extern "C" void kernel_launch(void* const* d_in, const int* in_sizes, int n_in,
                              void* d_out, int out_size) {
    const int*   pos_u    = (const int*)d_in[0];
    const int*   pos_w    = (const int*)d_in[1];
    const int*   neg_u    = (const int*)d_in[2];
    const int*   neg_w    = (const int*)d_in[3];
    const float* u_weight = (const float*)d_in[4];
    const float* w_weight = (const float*)d_in[5];
    float* out = (float*)d_out;

    cbow_loss_kernel<<<NBLOCKS, NTHREADS>>>(pos_u, pos_w, neg_u, neg_w,
                                            u_weight, w_weight, out);
}